// round 1
// baseline (speedup 1.0000x reference)
#include <cuda_runtime.h>
#include <cuda_bf16.h>
#include <cstdint>
#include <math.h>

#define D      2048
#define BROWS  2048
#define SIZE   6144
#define BIJ    4096
#define TILE   128
#define KC     64
#define KSTRIDE 72   // padded bf16 row stride in smem (144B -> conflict-free quad pattern)

// Scratch (device globals: allocation-free per harness rules)
__device__ __nv_bfloat16 g_z[(size_t)SIZE * D];   // normalized embeddings, bf16
__device__ float g_denom[SIZE];
__device__ float g_num[SIZE];

__device__ __forceinline__ float fast_ex2(float x) {
    float y;
    asm("ex2.approx.ftz.f32 %0, %1;" : "=f"(y) : "f"(x));
    return y;
}

__device__ __forceinline__ void mma_bf16(float c[4], const uint32_t a[4], const uint32_t b[2]) {
    asm volatile(
        "mma.sync.aligned.m16n8k16.row.col.f32.bf16.bf16.f32 "
        "{%0,%1,%2,%3}, {%4,%5,%6,%7}, {%8,%9}, {%0,%1,%2,%3};"
        : "+f"(c[0]), "+f"(c[1]), "+f"(c[2]), "+f"(c[3])
        : "r"(a[0]), "r"(a[1]), "r"(a[2]), "r"(a[3]), "r"(b[0]), "r"(b[1]));
}

// ---------------------------------------------------------------------------
// Kernel 1: L2-normalize rows -> bf16 z; zero accumulators.
// One block per row (6144 blocks, 256 threads).
// ---------------------------------------------------------------------------
__global__ void k_normalize(const float* __restrict__ e0,
                            const float* __restrict__ e1,
                            const float* __restrict__ e2) {
    int row = blockIdx.x;
    int tid = threadIdx.x;
    if (tid == 0) { g_denom[row] = 0.f; g_num[row] = 0.f; }

    const float* src;
    if (row < BROWS)            src = e0 + (size_t)row * D;
    else if (row < 2 * BROWS)   src = e1 + (size_t)(row - BROWS) * D;
    else                        src = e2 + (size_t)(row - 2 * BROWS) * D;

    float4 v0 = ((const float4*)src)[tid];
    float4 v1 = ((const float4*)src)[tid + 256];
    float ss = v0.x * v0.x + v0.y * v0.y + v0.z * v0.z + v0.w * v0.w
             + v1.x * v1.x + v1.y * v1.y + v1.z * v1.z + v1.w * v1.w;

    #pragma unroll
    for (int o = 16; o; o >>= 1) ss += __shfl_xor_sync(0xffffffffu, ss, o);

    __shared__ float ws[8];
    __shared__ float stot;
    if ((tid & 31) == 0) ws[tid >> 5] = ss;
    __syncthreads();
    if (tid == 0) {
        float t = ws[0] + ws[1] + ws[2] + ws[3] + ws[4] + ws[5] + ws[6] + ws[7];
        stot = t;
    }
    __syncthreads();

    float inv = 1.0f / fmaxf(sqrtf(stot), 1e-12f);

    __nv_bfloat162* dst = (__nv_bfloat162*)(g_z + (size_t)row * D);
    dst[tid * 2 + 0]       = __floats2bfloat162_rn(v0.x * inv, v0.y * inv);
    dst[tid * 2 + 1]       = __floats2bfloat162_rn(v0.z * inv, v0.w * inv);
    dst[(tid + 256) * 2]   = __floats2bfloat162_rn(v1.x * inv, v1.y * inv);
    dst[(tid + 256) * 2 + 1] = __floats2bfloat162_rn(v1.z * inv, v1.w * inv);
}

// ---------------------------------------------------------------------------
// Kernel 2: one 128x128 tile of e = exp(10 * z z^T) per block, fused row sums.
// 256 threads = 8 warps arranged 2(M) x 4(N); each warp owns 64x32 output.
// ---------------------------------------------------------------------------
__global__ __launch_bounds__(256, 2)
void k_sim() {
    __shared__ __nv_bfloat16 As[TILE * KSTRIDE];
    __shared__ __nv_bfloat16 Bs[TILE * KSTRIDE];
    __shared__ float rs[TILE];

    const int rowBase = blockIdx.y * TILE;
    const int colBase = blockIdx.x * TILE;
    const int tid  = threadIdx.x;
    const int wid  = tid >> 5;
    const int lane = tid & 31;
    const int mBase = (wid >> 2) * 64;   // warpM in {0,1}
    const int nBase = (wid & 3) * 32;    // warpN in {0..3}
    const int gid = lane >> 2;           // groupID 0..7
    const int tig = lane & 3;            // thread-in-group 0..3

    float acc[4][4][4] = {};             // [msub][nsub][frag]

    for (int k0 = 0; k0 < D; k0 += KC) {
        __syncthreads();
        // Stage A (rows of row-tile) and B (rows of col-tile): 128 x 64 bf16 each
        #pragma unroll
        for (int i = 0; i < 4; i++) {
            int id = tid + i * 256;      // 0..1023
            int r  = id >> 3;            // 0..127
            int vc = (id & 7) * 8;       // 0..56
            *(uint4*)(As + r * KSTRIDE + vc) =
                *(const uint4*)(g_z + (size_t)(rowBase + r) * D + k0 + vc);
            *(uint4*)(Bs + r * KSTRIDE + vc) =
                *(const uint4*)(g_z + (size_t)(colBase + r) * D + k0 + vc);
        }
        __syncthreads();

        #pragma unroll
        for (int kk = 0; kk < KC; kk += 16) {
            uint32_t a[4][4];
            uint32_t b[4][2];
            #pragma unroll
            for (int ms = 0; ms < 4; ms++) {
                int r = mBase + ms * 16 + gid;
                a[ms][0] = *(const uint32_t*)(As + r * KSTRIDE + kk + tig * 2);
                a[ms][1] = *(const uint32_t*)(As + (r + 8) * KSTRIDE + kk + tig * 2);
                a[ms][2] = *(const uint32_t*)(As + r * KSTRIDE + kk + 8 + tig * 2);
                a[ms][3] = *(const uint32_t*)(As + (r + 8) * KSTRIDE + kk + 8 + tig * 2);
            }
            #pragma unroll
            for (int ns = 0; ns < 4; ns++) {
                int n = nBase + ns * 8 + gid;
                b[ns][0] = *(const uint32_t*)(Bs + n * KSTRIDE + kk + tig * 2);
                b[ns][1] = *(const uint32_t*)(Bs + n * KSTRIDE + kk + 8 + tig * 2);
            }
            #pragma unroll
            for (int ms = 0; ms < 4; ms++)
                #pragma unroll
                for (int ns = 0; ns < 4; ns++)
                    mma_bf16(acc[ms][ns], a[ms], b[ns]);
        }
    }

    // exp, diagonal exclusion, row sums
    const bool diagTile = (rowBase == colBase);
    const float SCALE = 14.4269504088896340736f;   // 10 * log2(e)

    if (tid < TILE) rs[tid] = 0.f;
    __syncthreads();

    #pragma unroll
    for (int ms = 0; ms < 4; ms++) {
        int r0 = mBase + ms * 16 + gid;      // in-tile row (and r0+8)
        float s0 = 0.f, s1 = 0.f;
        #pragma unroll
        for (int ns = 0; ns < 4; ns++) {
            int c0 = nBase + ns * 8 + tig * 2;   // in-tile col (and c0+1)
            #pragma unroll
            for (int q = 0; q < 4; q++) {
                float v = fast_ex2(acc[ms][ns][q] * SCALE);
                int rr = (q >= 2) ? (r0 + 8) : r0;
                int cc = c0 + (q & 1);
                if (diagTile && rr == cc) v = 0.f;
                if (q < 2) s0 += v; else s1 += v;
            }
        }
        s0 += __shfl_xor_sync(0xffffffffu, s0, 1);
        s0 += __shfl_xor_sync(0xffffffffu, s0, 2);
        s1 += __shfl_xor_sync(0xffffffffu, s1, 1);
        s1 += __shfl_xor_sync(0xffffffffu, s1, 2);
        if (tig == 0) {
            atomicAdd(&rs[r0], s0);
            atomicAdd(&rs[r0 + 8], s1);
        }
    }
    __syncthreads();

    if (tid < TILE) {
        float v = rs[tid];
        atomicAdd(&g_denom[rowBase + tid], v);
        bool inNum = ((rowBase < BIJ) == (colBase < BIJ));
        if (inNum) atomicAdd(&g_num[rowBase + tid], v);
    }
}

// ---------------------------------------------------------------------------
// Kernel 3: per-row loss and final scalar.
// loss_i = log(denom_i) - log(num_i) + log(cnt_i - 1); out = sum / SIZE
// ---------------------------------------------------------------------------
__global__ void k_loss(float* __restrict__ out) {
    int tid = threadIdx.x;
    float s = 0.f;
    for (int i = tid; i < SIZE; i += 256) {
        float cntm1 = (i < BIJ) ? (float)(BIJ - 1) : (float)(BROWS - 1);
        s += logf(g_denom[i]) - logf(g_num[i]) + logf(cntm1);
    }
    #pragma unroll
    for (int o = 16; o; o >>= 1) s += __shfl_xor_sync(0xffffffffu, s, o);
    __shared__ float ws[8];
    if ((tid & 31) == 0) ws[tid >> 5] = s;
    __syncthreads();
    if (tid == 0) {
        float t = ws[0] + ws[1] + ws[2] + ws[3] + ws[4] + ws[5] + ws[6] + ws[7];
        out[0] = t / (float)SIZE;
    }
}

// ---------------------------------------------------------------------------
extern "C" void kernel_launch(void* const* d_in, const int* in_sizes, int n_in,
                              void* d_out, int out_size) {
    const float* emb_i = (const float*)d_in[0];
    const float* emb_j = (const float*)d_in[1];
    const float* emb_k = (const float*)d_in[2];
    float* out = (float*)d_out;

    k_normalize<<<SIZE, 256>>>(emb_i, emb_j, emb_k);
    dim3 grid(SIZE / TILE, SIZE / TILE);
    k_sim<<<grid, 256>>>();
    k_loss<<<1, 256>>>(out);
}

// round 2
// speedup vs baseline: 1.8850x; 1.8850x over previous
#include <cuda_runtime.h>
#include <cuda_bf16.h>
#include <cstdint>
#include <math.h>

#define D      2048
#define BROWS  2048
#define SIZE   6144
#define BIJ    4096
#define TILE   128
#define KC     64
#define KSTRIDE 72   // padded bf16 row stride in smem (144B -> conflict-free quad pattern)
#define NTILES 48
#define NBLOCKS (NTILES * (NTILES + 1) / 2)   // 1176 upper-triangle tiles

// Scratch (device globals: allocation-free per harness rules)
__device__ __nv_bfloat16 g_z[(size_t)SIZE * D];   // normalized embeddings, bf16
__device__ float g_denom[SIZE];
__device__ float g_num[SIZE];

__device__ __forceinline__ float fast_ex2(float x) {
    float y;
    asm("ex2.approx.ftz.f32 %0, %1;" : "=f"(y) : "f"(x));
    return y;
}

__device__ __forceinline__ void mma_bf16(float c[4], const uint32_t a[4], const uint32_t b[2]) {
    asm volatile(
        "mma.sync.aligned.m16n8k16.row.col.f32.bf16.bf16.f32 "
        "{%0,%1,%2,%3}, {%4,%5,%6,%7}, {%8,%9}, {%0,%1,%2,%3};"
        : "+f"(c[0]), "+f"(c[1]), "+f"(c[2]), "+f"(c[3])
        : "r"(a[0]), "r"(a[1]), "r"(a[2]), "r"(a[3]), "r"(b[0]), "r"(b[1]));
}

// ---------------------------------------------------------------------------
// Kernel 1: L2-normalize rows -> bf16 z; zero accumulators.
// ---------------------------------------------------------------------------
__global__ void k_normalize(const float* __restrict__ e0,
                            const float* __restrict__ e1,
                            const float* __restrict__ e2) {
    int row = blockIdx.x;
    int tid = threadIdx.x;
    if (tid == 0) { g_denom[row] = 0.f; g_num[row] = 0.f; }

    const float* src;
    if (row < BROWS)            src = e0 + (size_t)row * D;
    else if (row < 2 * BROWS)   src = e1 + (size_t)(row - BROWS) * D;
    else                        src = e2 + (size_t)(row - 2 * BROWS) * D;

    float4 v0 = ((const float4*)src)[tid];
    float4 v1 = ((const float4*)src)[tid + 256];
    float ss = v0.x * v0.x + v0.y * v0.y + v0.z * v0.z + v0.w * v0.w
             + v1.x * v1.x + v1.y * v1.y + v1.z * v1.z + v1.w * v1.w;

    #pragma unroll
    for (int o = 16; o; o >>= 1) ss += __shfl_xor_sync(0xffffffffu, ss, o);

    __shared__ float ws[8];
    __shared__ float stot;
    if ((tid & 31) == 0) ws[tid >> 5] = ss;
    __syncthreads();
    if (tid == 0) {
        stot = ws[0] + ws[1] + ws[2] + ws[3] + ws[4] + ws[5] + ws[6] + ws[7];
    }
    __syncthreads();

    float inv = 1.0f / fmaxf(sqrtf(stot), 1e-12f);

    __nv_bfloat162* dst = (__nv_bfloat162*)(g_z + (size_t)row * D);
    dst[tid * 2 + 0]         = __floats2bfloat162_rn(v0.x * inv, v0.y * inv);
    dst[tid * 2 + 1]         = __floats2bfloat162_rn(v0.z * inv, v0.w * inv);
    dst[(tid + 256) * 2]     = __floats2bfloat162_rn(v1.x * inv, v1.y * inv);
    dst[(tid + 256) * 2 + 1] = __floats2bfloat162_rn(v1.z * inv, v1.w * inv);
}

// ---------------------------------------------------------------------------
// Kernel 2: upper-triangle tiles only (symmetry). Each off-diagonal tile
// contributes its row sums to rows [rowBase,.] AND its column sums to rows
// [colBase,.] (since e is symmetric). 256 threads = 8 warps, 2(M) x 4(N).
// ---------------------------------------------------------------------------
__global__ __launch_bounds__(256, 2)
void k_sim() {
    __shared__ __nv_bfloat16 As[TILE * KSTRIDE];
    __shared__ __nv_bfloat16 Bs[TILE * KSTRIDE];
    __shared__ float rs[TILE];
    __shared__ float cs[TILE];

    // Triangular decode: t = i*(i+1)/2 + j with j <= i; rowTile=j, colTile=i
    int t = blockIdx.x;
    int i = (int)((sqrtf(8.0f * (float)t + 1.0f) - 1.0f) * 0.5f);
    while ((i + 1) * (i + 2) / 2 <= t) i++;
    while (i * (i + 1) / 2 > t) i--;
    int j = t - i * (i + 1) / 2;

    const int rowBase = j * TILE;
    const int colBase = i * TILE;
    const bool diagTile = (i == j);

    const int tid  = threadIdx.x;
    const int wid  = tid >> 5;
    const int lane = tid & 31;
    const int mBase = (wid >> 2) * 64;   // warpM in {0,1}
    const int nBase = (wid & 3) * 32;    // warpN in {0..3}
    const int gid = lane >> 2;           // groupID 0..7
    const int tig = lane & 3;            // thread-in-group 0..3

    float acc[4][4][4] = {};             // [msub][nsub][frag]

    for (int k0 = 0; k0 < D; k0 += KC) {
        __syncthreads();
        #pragma unroll
        for (int it = 0; it < 4; it++) {
            int id = tid + it * 256;     // 0..1023
            int r  = id >> 3;            // 0..127
            int vc = (id & 7) * 8;       // 0..56
            *(uint4*)(As + r * KSTRIDE + vc) =
                *(const uint4*)(g_z + (size_t)(rowBase + r) * D + k0 + vc);
            *(uint4*)(Bs + r * KSTRIDE + vc) =
                *(const uint4*)(g_z + (size_t)(colBase + r) * D + k0 + vc);
        }
        __syncthreads();

        #pragma unroll
        for (int kk = 0; kk < KC; kk += 16) {
            uint32_t a[4][4];
            uint32_t b[4][2];
            #pragma unroll
            for (int ms = 0; ms < 4; ms++) {
                int r = mBase + ms * 16 + gid;
                a[ms][0] = *(const uint32_t*)(As + r * KSTRIDE + kk + tig * 2);
                a[ms][1] = *(const uint32_t*)(As + (r + 8) * KSTRIDE + kk + tig * 2);
                a[ms][2] = *(const uint32_t*)(As + r * KSTRIDE + kk + 8 + tig * 2);
                a[ms][3] = *(const uint32_t*)(As + (r + 8) * KSTRIDE + kk + 8 + tig * 2);
            }
            #pragma unroll
            for (int ns = 0; ns < 4; ns++) {
                int n = nBase + ns * 8 + gid;
                b[ns][0] = *(const uint32_t*)(Bs + n * KSTRIDE + kk + tig * 2);
                b[ns][1] = *(const uint32_t*)(Bs + n * KSTRIDE + kk + 8 + tig * 2);
            }
            #pragma unroll
            for (int ms = 0; ms < 4; ms++)
                #pragma unroll
                for (int ns = 0; ns < 4; ns++)
                    mma_bf16(acc[ms][ns], a[ms], b[ns]);
        }
    }

    // exp, diagonal exclusion, row + column sums
    const float SCALE = 14.4269504088896340736f;   // 10 * log2(e)

    if (tid < TILE) { rs[tid] = 0.f; cs[tid] = 0.f; }
    __syncthreads();

    float colAcc[4][2] = {};   // per-thread column partials [ns][c parity]

    #pragma unroll
    for (int ms = 0; ms < 4; ms++) {
        int r0 = mBase + ms * 16 + gid;      // in-tile row (and r0+8)
        float s0 = 0.f, s1 = 0.f;
        #pragma unroll
        for (int ns = 0; ns < 4; ns++) {
            int c0 = nBase + ns * 8 + tig * 2;   // in-tile col (and c0+1)
            float v0 = fast_ex2(acc[ms][ns][0] * SCALE);
            float v1 = fast_ex2(acc[ms][ns][1] * SCALE);
            float v2 = fast_ex2(acc[ms][ns][2] * SCALE);
            float v3 = fast_ex2(acc[ms][ns][3] * SCALE);
            if (diagTile) {
                if (r0 == c0)         v0 = 0.f;
                if (r0 == c0 + 1)     v1 = 0.f;
                if (r0 + 8 == c0)     v2 = 0.f;
                if (r0 + 8 == c0 + 1) v3 = 0.f;
            }
            s0 += v0 + v1;
            s1 += v2 + v3;
            colAcc[ns][0] += v0 + v2;
            colAcc[ns][1] += v1 + v3;
        }
        // row-sum reduce across tig (lanes differing in bits 0,1)
        s0 += __shfl_xor_sync(0xffffffffu, s0, 1);
        s0 += __shfl_xor_sync(0xffffffffu, s0, 2);
        s1 += __shfl_xor_sync(0xffffffffu, s1, 1);
        s1 += __shfl_xor_sync(0xffffffffu, s1, 2);
        if (tig == 0) {
            atomicAdd(&rs[r0], s0);
            atomicAdd(&rs[r0 + 8], s1);
        }
    }

    // column-sum reduce across gid (lanes differing in bits 2,3,4)
    if (!diagTile) {
        #pragma unroll
        for (int ns = 0; ns < 4; ns++) {
            float c0v = colAcc[ns][0];
            float c1v = colAcc[ns][1];
            #pragma unroll
            for (int o = 4; o <= 16; o <<= 1) {
                c0v += __shfl_xor_sync(0xffffffffu, c0v, o);
                c1v += __shfl_xor_sync(0xffffffffu, c1v, o);
            }
            if (gid == 0) {
                int c0 = nBase + ns * 8 + tig * 2;
                atomicAdd(&cs[c0], c0v);
                atomicAdd(&cs[c0 + 1], c1v);
            }
        }
    }
    __syncthreads();

    if (tid < TILE) {
        bool inNum = ((rowBase < BIJ) == (colBase < BIJ));
        float rv = rs[tid];
        atomicAdd(&g_denom[rowBase + tid], rv);
        if (inNum) atomicAdd(&g_num[rowBase + tid], rv);
        if (!diagTile) {
            float cv = cs[tid];
            atomicAdd(&g_denom[colBase + tid], cv);
            if (inNum) atomicAdd(&g_num[colBase + tid], cv);
        }
    }
}

// ---------------------------------------------------------------------------
// Kernel 3: per-row loss and final scalar.
// ---------------------------------------------------------------------------
__global__ void k_loss(float* __restrict__ out) {
    int tid = threadIdx.x;
    float s = 0.f;
    for (int ii = tid; ii < SIZE; ii += 256) {
        float cntm1 = (ii < BIJ) ? (float)(BIJ - 1) : (float)(BROWS - 1);
        s += logf(g_denom[ii]) - logf(g_num[ii]) + logf(cntm1);
    }
    #pragma unroll
    for (int o = 16; o; o >>= 1) s += __shfl_xor_sync(0xffffffffu, s, o);
    __shared__ float ws[8];
    if ((tid & 31) == 0) ws[tid >> 5] = s;
    __syncthreads();
    if (tid == 0) {
        float tsum = ws[0] + ws[1] + ws[2] + ws[3] + ws[4] + ws[5] + ws[6] + ws[7];
        out[0] = tsum / (float)SIZE;
    }
}

// ---------------------------------------------------------------------------
extern "C" void kernel_launch(void* const* d_in, const int* in_sizes, int n_in,
                              void* d_out, int out_size) {
    const float* emb_i = (const float*)d_in[0];
    const float* emb_j = (const float*)d_in[1];
    const float* emb_k = (const float*)d_in[2];
    float* out = (float*)d_out;

    k_normalize<<<SIZE, 256>>>(emb_i, emb_j, emb_k);
    k_sim<<<NBLOCKS, 256>>>();
    k_loss<<<1, 256>>>(out);
}

// round 5
// speedup vs baseline: 2.2175x; 1.1764x over previous
#include <cuda_runtime.h>
#include <cuda_bf16.h>
#include <cstdint>
#include <math.h>

#define D      2048
#define BROWS  2048
#define SIZE   6144
#define BIJ    4096
#define TILE   128
#define KC     64
#define NCHUNK (D / KC)               // 32
#define RSTRIDE 144                   // bytes per staged row (72 bf16, conflict-free)
#define NTILES 48
#define NBLOCKS (NTILES * (NTILES + 1) / 2)   // 1176 upper-triangle tiles

// dynamic smem layout (bytes): A0,B0,A1,B1 (18432 each), rs (512), cs (512)
#define BUFSZ   (TILE * RSTRIDE)      // 18432
#define OFF_A0  0
#define OFF_B0  BUFSZ
#define OFF_A1  (2 * BUFSZ)
#define OFF_B1  (3 * BUFSZ)
#define OFF_RS  (4 * BUFSZ)
#define OFF_CS  (4 * BUFSZ + 512)
#define SMEM_TOTAL (4 * BUFSZ + 1024)

// Scratch (device globals: allocation-free per harness rules)
__device__ __nv_bfloat16 g_z[(size_t)SIZE * D];
__device__ float g_denom[SIZE];
__device__ float g_num[SIZE];

__device__ __forceinline__ uint32_t smem_u32(const void* p) {
    uint32_t a;
    asm("{ .reg .u64 t; cvta.to.shared.u64 t, %1; cvt.u32.u64 %0, t; }" : "=r"(a) : "l"(p));
    return a;
}
__device__ __forceinline__ float fast_ex2(float x) {
    float y; asm("ex2.approx.ftz.f32 %0, %1;" : "=f"(y) : "f"(x)); return y;
}
__device__ __forceinline__ void cp16(uint32_t dst, const void* src) {
    asm volatile("cp.async.cg.shared.global [%0], [%1], 16;" :: "r"(dst), "l"(src));
}
#define CP_COMMIT()  asm volatile("cp.async.commit_group;" ::: "memory")
#define CP_WAIT1()   asm volatile("cp.async.wait_group 1;" ::: "memory")
#define CP_WAIT0()   asm volatile("cp.async.wait_group 0;" ::: "memory")

__device__ __forceinline__ void ldsm4(uint32_t* r, uint32_t addr) {
    asm volatile("ldmatrix.sync.aligned.m8n8.x4.shared.b16 {%0,%1,%2,%3}, [%4];"
                 : "=r"(r[0]), "=r"(r[1]), "=r"(r[2]), "=r"(r[3]) : "r"(addr));
}
__device__ __forceinline__ void mma_bf16(float c[4], const uint32_t a[4], const uint32_t b[2]) {
    asm volatile(
        "mma.sync.aligned.m16n8k16.row.col.f32.bf16.bf16.f32 "
        "{%0,%1,%2,%3}, {%4,%5,%6,%7}, {%8,%9}, {%0,%1,%2,%3};"
        : "+f"(c[0]), "+f"(c[1]), "+f"(c[2]), "+f"(c[3])
        : "r"(a[0]), "r"(a[1]), "r"(a[2]), "r"(a[3]), "r"(b[0]), "r"(b[1]));
}

// ---------------------------------------------------------------------------
// Kernel 1: L2-normalize rows -> bf16 z; zero accumulators.
// ---------------------------------------------------------------------------
__global__ void k_normalize(const float* __restrict__ e0,
                            const float* __restrict__ e1,
                            const float* __restrict__ e2) {
    int row = blockIdx.x;
    int tid = threadIdx.x;
    if (tid == 0) { g_denom[row] = 0.f; g_num[row] = 0.f; }

    const float* src;
    if (row < BROWS)            src = e0 + (size_t)row * D;
    else if (row < 2 * BROWS)   src = e1 + (size_t)(row - BROWS) * D;
    else                        src = e2 + (size_t)(row - 2 * BROWS) * D;

    float4 v0 = ((const float4*)src)[tid];
    float4 v1 = ((const float4*)src)[tid + 256];
    float ss = v0.x * v0.x + v0.y * v0.y + v0.z * v0.z + v0.w * v0.w
             + v1.x * v1.x + v1.y * v1.y + v1.z * v1.z + v1.w * v1.w;

    #pragma unroll
    for (int o = 16; o; o >>= 1) ss += __shfl_xor_sync(0xffffffffu, ss, o);

    __shared__ float ws[8];
    __shared__ float stot;
    if ((tid & 31) == 0) ws[tid >> 5] = ss;
    __syncthreads();
    if (tid == 0) stot = ws[0] + ws[1] + ws[2] + ws[3] + ws[4] + ws[5] + ws[6] + ws[7];
    __syncthreads();

    float inv = 1.0f / fmaxf(sqrtf(stot), 1e-12f);

    __nv_bfloat162* dst = (__nv_bfloat162*)(g_z + (size_t)row * D);
    dst[tid * 2 + 0]         = __floats2bfloat162_rn(v0.x * inv, v0.y * inv);
    dst[tid * 2 + 1]         = __floats2bfloat162_rn(v0.z * inv, v0.w * inv);
    dst[(tid + 256) * 2]     = __floats2bfloat162_rn(v1.x * inv, v1.y * inv);
    dst[(tid + 256) * 2 + 1] = __floats2bfloat162_rn(v1.z * inv, v1.w * inv);
}

// ---------------------------------------------------------------------------
// Kernel 2: upper-triangle tiles, cp.async double-buffered, ldmatrix frags.
// 256 threads = 8 warps, 2(M) x 4(N), each warp 64x32 of the 128x128 tile.
// ---------------------------------------------------------------------------
__device__ __forceinline__ void stage_chunk(uint32_t sb, uint32_t aOff, uint32_t bOff,
                                            int rowBase, int colBase, int k0, int tid) {
    #pragma unroll
    for (int it = 0; it < 4; it++) {
        int id = tid + it * 256;          // 0..1023
        int r  = id >> 3;                 // 0..127
        int c  = id & 7;                  // 16B sub-chunk
        uint32_t o = (uint32_t)(r * RSTRIDE + c * 16);
        cp16(sb + aOff + o, g_z + (size_t)(rowBase + r) * D + k0 + c * 8);
        cp16(sb + bOff + o, g_z + (size_t)(colBase + r) * D + k0 + c * 8);
    }
}

__global__ __launch_bounds__(256, 2)
void k_sim() {
    extern __shared__ char smem[];
    const uint32_t sb = smem_u32(smem);
    float* rs = (float*)(smem + OFF_RS);
    float* cs = (float*)(smem + OFF_CS);

    // Triangular decode: t = i*(i+1)/2 + j with j <= i; rowTile=j, colTile=i
    int t = blockIdx.x;
    int i = (int)((sqrtf(8.0f * (float)t + 1.0f) - 1.0f) * 0.5f);
    while ((i + 1) * (i + 2) / 2 <= t) i++;
    while (i * (i + 1) / 2 > t) i--;
    int j = t - i * (i + 1) / 2;

    const int rowBase = j * TILE;
    const int colBase = i * TILE;
    const bool diagTile = (i == j);

    const int tid  = threadIdx.x;
    const int wid  = tid >> 5;
    const int lane = tid & 31;
    const int mBase = (wid >> 2) * 64;   // warpM in {0,1}
    const int nBase = (wid & 3) * 32;    // warpN in {0..3}
    const int gid = lane >> 2;
    const int tig = lane & 3;

    if (tid < 2 * TILE) ((float*)(smem + OFF_RS))[tid] = 0.f;

    // ldmatrix lane base addresses (byte offsets within a buffer)
    const uint32_t aLaneOff =
        (uint32_t)((mBase + (lane & 15)) * RSTRIDE + ((lane & 16) ? 16 : 0));
    const uint32_t bLaneOff =
        (uint32_t)((nBase + ((lane & 16) ? 8 : 0) + (lane & 7)) * RSTRIDE + ((lane & 8) ? 16 : 0));

    float acc[4][4][4] = {};             // [msub][nsub][frag]

    // prologue: prefetch chunk 0 into buffer 0
    stage_chunk(sb, OFF_A0, OFF_B0, rowBase, colBase, 0, tid);
    CP_COMMIT();

    for (int c = 0; c < NCHUNK; c++) {
        const int buf = c & 1;
        const uint32_t aOff = buf ? OFF_A1 : OFF_A0;
        const uint32_t bOff = buf ? OFF_B1 : OFF_B0;

        if (c + 1 < NCHUNK) {
            stage_chunk(sb, buf ? OFF_A0 : OFF_A1, buf ? OFF_B0 : OFF_B1,
                        rowBase, colBase, (c + 1) * KC, tid);
            CP_COMMIT();
            CP_WAIT1();
        } else {
            CP_WAIT0();
        }
        __syncthreads();

        const uint32_t aB = sb + aOff + aLaneOff;
        const uint32_t bB = sb + bOff + bLaneOff;

        #pragma unroll
        for (int kk = 0; kk < KC; kk += 16) {
            uint32_t a[4][4];
            uint32_t b[2][4];            // [pair][ (ns even:0,1) (ns odd:2,3) ]
            #pragma unroll
            for (int ms = 0; ms < 4; ms++)
                ldsm4(a[ms], aB + ms * (16 * RSTRIDE) + kk * 2);
            #pragma unroll
            for (int p = 0; p < 2; p++)
                ldsm4(b[p], bB + p * (16 * RSTRIDE) + kk * 2);

            #pragma unroll
            for (int ms = 0; ms < 4; ms++) {
                mma_bf16(acc[ms][0], a[ms], &b[0][0]);
                mma_bf16(acc[ms][1], a[ms], &b[0][2]);
                mma_bf16(acc[ms][2], a[ms], &b[1][0]);
                mma_bf16(acc[ms][3], a[ms], &b[1][2]);
            }
        }
        __syncthreads();   // all warps done reading buf before it is re-staged
    }

    // exp, diagonal exclusion, row + column sums
    const float SCALE = 14.4269504088896340736f;   // 10 * log2(e)

    float colAcc[4][2] = {};

    #pragma unroll
    for (int ms = 0; ms < 4; ms++) {
        int r0 = mBase + ms * 16 + gid;
        float s0 = 0.f, s1 = 0.f;
        #pragma unroll
        for (int ns = 0; ns < 4; ns++) {
            int c0 = nBase + ns * 8 + tig * 2;
            float v0 = fast_ex2(acc[ms][ns][0] * SCALE);
            float v1 = fast_ex2(acc[ms][ns][1] * SCALE);
            float v2 = fast_ex2(acc[ms][ns][2] * SCALE);
            float v3 = fast_ex2(acc[ms][ns][3] * SCALE);
            if (diagTile) {
                if (r0 == c0)         v0 = 0.f;
                if (r0 == c0 + 1)     v1 = 0.f;
                if (r0 + 8 == c0)     v2 = 0.f;
                if (r0 + 8 == c0 + 1) v3 = 0.f;
            }
            s0 += v0 + v1;
            s1 += v2 + v3;
            colAcc[ns][0] += v0 + v2;
            colAcc[ns][1] += v1 + v3;
        }
        s0 += __shfl_xor_sync(0xffffffffu, s0, 1);
        s0 += __shfl_xor_sync(0xffffffffu, s0, 2);
        s1 += __shfl_xor_sync(0xffffffffu, s1, 1);
        s1 += __shfl_xor_sync(0xffffffffu, s1, 2);
        if (tig == 0) {
            atomicAdd(&rs[r0], s0);
            atomicAdd(&rs[r0 + 8], s1);
        }
    }

    if (!diagTile) {
        #pragma unroll
        for (int ns = 0; ns < 4; ns++) {
            float c0v = colAcc[ns][0];
            float c1v = colAcc[ns][1];
            #pragma unroll
            for (int o = 4; o <= 16; o <<= 1) {
                c0v += __shfl_xor_sync(0xffffffffu, c0v, o);
                c1v += __shfl_xor_sync(0xffffffffu, c1v, o);
            }
            if (gid == 0) {
                int c0 = nBase + ns * 8 + tig * 2;
                atomicAdd(&cs[c0], c0v);
                atomicAdd(&cs[c0 + 1], c1v);
            }
        }
    }
    __syncthreads();

    if (tid < TILE) {
        bool inNum = ((rowBase < BIJ) == (colBase < BIJ));
        float rv = rs[tid];
        atomicAdd(&g_denom[rowBase + tid], rv);
        if (inNum) atomicAdd(&g_num[rowBase + tid], rv);
        if (!diagTile) {
            float cv = cs[tid];
            atomicAdd(&g_denom[colBase + tid], cv);
            if (inNum) atomicAdd(&g_num[colBase + tid], cv);
        }
    }
}

// ---------------------------------------------------------------------------
// Kernel 3: per-row loss and final scalar.
// ---------------------------------------------------------------------------
__global__ void k_loss(float* __restrict__ out) {
    int tid = threadIdx.x;
    float s = 0.f;
    for (int ii = tid; ii < SIZE; ii += 256) {
        float cntm1 = (ii < BIJ) ? (float)(BIJ - 1) : (float)(BROWS - 1);
        s += logf(g_denom[ii]) - logf(g_num[ii]) + logf(cntm1);
    }
    #pragma unroll
    for (int o = 16; o; o >>= 1) s += __shfl_xor_sync(0xffffffffu, s, o);
    __shared__ float ws[8];
    if ((tid & 31) == 0) ws[tid >> 5] = s;
    __syncthreads();
    if (tid == 0) {
        float tsum = ws[0] + ws[1] + ws[2] + ws[3] + ws[4] + ws[5] + ws[6] + ws[7];
        out[0] = tsum / (float)SIZE;
    }
}

// ---------------------------------------------------------------------------
extern "C" void kernel_launch(void* const* d_in, const int* in_sizes, int n_in,
                              void* d_out, int out_size) {
    const float* emb_i = (const float*)d_in[0];
    const float* emb_j = (const float*)d_in[1];
    const float* emb_k = (const float*)d_in[2];
    float* out = (float*)d_out;

    cudaFuncSetAttribute(k_sim, cudaFuncAttributeMaxDynamicSharedMemorySize, SMEM_TOTAL);

    k_normalize<<<SIZE, 256>>>(emb_i, emb_j, emb_k);
    k_sim<<<NBLOCKS, 256, SMEM_TOTAL>>>();
    k_loss<<<1, 256>>>(out);
}